// round 5
// baseline (speedup 1.0000x reference)
#include <cuda_runtime.h>
#include <math.h>

// Problem constants (fixed shapes from reference)
#define NQ      262144      // total queries = B*L*cg = 4*1024*64
#define NSAM    1024        // prior samples
#define NPAIR   512         // sample pairs (f32x2 packing)
#define TSTRIDE 8           // floats per pair row in smem table (32 B rows: S only)
#define THREADS 448
#define QPT     2           // queries per thread
#define CHUNK   32          // pairs per argmax chunk
#define NCHUNK  (NPAIR / CHUNK)
#define ZHAT_OFF   0
#define NOQ_OFF    1048576  // B*L*C
#define IDX_OFF    2097152  // 2*B*L*C
#define FULL_OUT   2359296  // + B*L*cg

// ---- packed f32x2 helpers (Blackwell FFMA2/FMUL2) ----
__device__ __forceinline__ unsigned long long ffma2(unsigned long long a,
                                                    unsigned long long b,
                                                    unsigned long long c) {
    unsigned long long d;
    asm("fma.rn.f32x2 %0, %1, %2, %3;" : "=l"(d) : "l"(a), "l"(b), "l"(c));
    return d;
}
__device__ __forceinline__ unsigned long long fmul2(unsigned long long a,
                                                    unsigned long long b) {
    unsigned long long d;
    asm("mul.rn.f32x2 %0, %1, %2;" : "=l"(d) : "l"(a), "l"(b));
    return d;
}
__device__ __forceinline__ unsigned long long pack2(float x) {
    unsigned long long r;
    asm("mov.b64 %0, {%1, %1};" : "=l"(r) : "f"(x));
    return r;
}
__device__ __forceinline__ float lo2(unsigned long long a) {
    return __uint_as_float((unsigned)(a & 0xffffffffull));
}
__device__ __forceinline__ float hi2(unsigned long long a) {
    return __uint_as_float((unsigned)(a >> 32));
}

// Factored score for one query against one sample pair:
//   acc = sum_g S_g * (u_g + vh_g * S_g)
// Both main loop and rescan use this exact sequence -> bit-identical results.
__device__ __forceinline__ unsigned long long score_pair(
        const unsigned long long* uu, const unsigned long long* vh,
        unsigned long long s0, unsigned long long s1,
        unsigned long long s2, unsigned long long s3) {
    unsigned long long t, a;
    t = ffma2(vh[0], s0, uu[0]);  a = fmul2(s0, t);
    t = ffma2(vh[1], s1, uu[1]);  a = ffma2(s1, t, a);
    t = ffma2(vh[2], s2, uu[2]);  a = ffma2(s2, t, a);
    t = ffma2(vh[3], s3, uu[3]);  a = ffma2(s3, t, a);
    return a;
}

// Recompute one chunk's scores for one query; return smallest global sample
// index whose score equals target exactly (lo lane checked before hi lane).
__device__ __forceinline__ int rescan_chunk(const float* __restrict__ tab,
                                            const unsigned long long* uu,
                                            const unsigned long long* vh,
                                            int chunk, float target) {
    int found = NSAM;    // min-reduce => first match
    #pragma unroll 4
    for (int t = 0; t < CHUNK; t++) {
        int p = chunk * CHUNK + t;
        const float* base = &tab[p * TSTRIDE];
        ulonglong2 wa = *reinterpret_cast<const ulonglong2*>(base + 0);   // S0,S1
        ulonglong2 wb = *reinterpret_cast<const ulonglong2*>(base + 4);   // S2,S3
        unsigned long long a = score_pair(uu, vh, wa.x, wa.y, wb.x, wb.y);
        int cand = (lo2(a) == target) ? 2 * p
                 : ((hi2(a) == target) ? 2 * p + 1 : NSAM);
        found = min(found, cand);
    }
    return found;
}

__global__ void __launch_bounds__(THREADS, 2)
gq_kernel(const float* __restrict__ z,
          const float* __restrict__ eps,
          const float* __restrict__ prior,
          float* __restrict__ out,
          int out_size)
{
    // Packed sample table: per pair p (= samples 2p, 2p+1), 4 f32x2 words:
    //   [S_g0 | S_g1 | S_g2 | S_g3]
    // All other terms folded into per-query coefficients:
    //   u_g = mu*e^{-lv},  vh_g = 0.5*(1 - e^{-lv})
    //   score ~ sum_g S*(u + vh*S)   (per-query/global constants dropped)
    __shared__ __align__(16) float tab[NPAIR * TSTRIDE];   // 16384 B per CTA

    const int tid = threadIdx.x;
    for (int n = tid; n < NSAM; n += THREADS) {
        float4 s = reinterpret_cast<const float4*>(prior)[n];
        int p = n >> 1, h = n & 1;
        float* t = &tab[p * TSTRIDE];
        t[0 + h] = s.x;  t[2 + h] = s.y;  t[4 + h] = s.z;  t[6 + h] = s.w;
    }

    // Each thread owns 2 consecutive queries k0, k0+1 (j even, never crosses a row)
    const int gtid = blockIdx.x * THREADS + tid;
    const int k0   = gtid * QPT;
    const bool valid = (k0 < NQ);
    const int bl = k0 >> 6;     // (b*L + l)
    const int j  = k0 & 63;

    // Packed per-query coefficients
    unsigned long long uu[QPT][4], vh[QPT][4];

    if (valid) {
        #pragma unroll
        for (int g = 0; g < 4; g++) {
            const int moff = bl * 512 + g * 64 + j;           // mu
            float2 mu2 = *reinterpret_cast<const float2*>(z + moff);
            float2 lv2 = *reinterpret_cast<const float2*>(z + moff + 256);
            lv2.x = fminf(fmaxf(lv2.x, -30.0f), 20.0f);
            lv2.y = fminf(fmaxf(lv2.y, -30.0f), 20.0f);
            float ivx = expf(-lv2.x), ivy = expf(-lv2.y);
            uu[0][g] = pack2(mu2.x * ivx);  vh[0][g] = pack2(0.5f * (1.0f - ivx));
            uu[1][g] = pack2(mu2.y * ivy);  vh[1][g] = pack2(0.5f * (1.0f - ivy));

            // Fused zhat_noquant = mu + eps * exp(0.5*logvar)
            const int eoff = bl * 256 + g * 64 + j;
            float2 e2 = *reinterpret_cast<const float2*>(eps + eoff);
            float2 nq;
            nq.x = fmaf(e2.x, expf(0.5f * lv2.x), mu2.x);
            nq.y = fmaf(e2.y, expf(0.5f * lv2.y), mu2.y);
            if (out_size >= IDX_OFF)
                *reinterpret_cast<float2*>(out + NOQ_OFF + eoff) = nq;
        }
    }
    __syncthreads();
    if (!valid) return;   // tail threads exit (no further barriers)

    const float NEG_INF = -__int_as_float(0x7f800000);
    // One running max per query; even/odd lane resolved in the rescan.
    float g0 = NEG_INF, g1 = NEG_INF;
    int   c0 = 0, c1 = 0;

    for (int ch = 0; ch < NCHUNK; ch++) {
        float m0 = NEG_INF, m1 = NEG_INF;
        const float* cbase = &tab[ch * CHUNK * TSTRIDE];
        #pragma unroll
        for (int t = 0; t < CHUNK; t += 2) {
            // Loads for both pairs first (independent; ptxas can prefetch ahead)
            const float* b0 = cbase + t * TSTRIDE;
            ulonglong2 wa0 = *reinterpret_cast<const ulonglong2*>(b0 + 0);
            ulonglong2 wb0 = *reinterpret_cast<const ulonglong2*>(b0 + 4);
            ulonglong2 wa1 = *reinterpret_cast<const ulonglong2*>(b0 + 8);
            ulonglong2 wb1 = *reinterpret_cast<const ulonglong2*>(b0 + 12);

            // 4 independent score chains (2 queries x 2 pairs)
            unsigned long long a00 = score_pair(uu[0], vh[0], wa0.x, wa0.y, wb0.x, wb0.y);
            unsigned long long a10 = score_pair(uu[1], vh[1], wa0.x, wa0.y, wb0.x, wb0.y);
            unsigned long long a01 = score_pair(uu[0], vh[0], wa1.x, wa1.y, wb1.x, wb1.y);
            unsigned long long a11 = score_pair(uu[1], vh[1], wa1.x, wa1.y, wb1.x, wb1.y);

            // Tournament, then one running-max update per query per 2 pairs
            float p0 = fmaxf(fmaxf(lo2(a00), hi2(a00)), fmaxf(lo2(a01), hi2(a01)));
            float p1 = fmaxf(fmaxf(lo2(a10), hi2(a10)), fmaxf(lo2(a11), hi2(a11)));
            m0 = fmaxf(m0, p0);
            m1 = fmaxf(m1, p1);
        }
        // Strict '>' keeps the earliest chunk on ties (first-index semantics)
        if (m0 > g0) { g0 = m0; c0 = ch; }
        if (m1 > g1) { g1 = m1; c1 = ch; }
    }

    // Resolve exact indices by rescanning each query's winning chunk
    int bidx[QPT];
    bidx[0] = rescan_chunk(tab, uu[0], vh[0], c0, g0);
    bidx[1] = rescan_chunk(tab, uu[1], vh[1], c1, g1);

    {
        // Gather winning prior rows (prior table is L2-hot, 16 KB)
        float r[QPT][4];
        #pragma unroll
        for (int q = 0; q < QPT; q++) {
            float4 s = reinterpret_cast<const float4*>(prior)[bidx[q]];
            r[q][0] = s.x; r[q][1] = s.y; r[q][2] = s.z; r[q][3] = s.w;
        }
        #pragma unroll
        for (int g = 0; g < 4; g++) {
            float2 o2 = make_float2(r[0][g], r[1][g]);
            *reinterpret_cast<float2*>(out + ZHAT_OFF + bl * 256 + g * 64 + j) = o2;
        }
        if (out_size >= FULL_OUT) {
            float2 i2 = make_float2((float)bidx[0], (float)bidx[1]);
            *reinterpret_cast<float2*>(out + IDX_OFF + k0) = i2;
        }
    }
}

extern "C" void kernel_launch(void* const* d_in, const int* in_sizes, int n_in,
                              void* d_out, int out_size) {
    const float* z     = (const float*)d_in[0];
    const float* eps   = (const float*)d_in[1];
    const float* prior = (const float*)d_in[2];
    (void)in_sizes; (void)n_in;
    const int thread_slots = NQ / QPT;                         // 131072
    const int blocks = (thread_slots + THREADS - 1) / THREADS; // 293 -> 2 CTAs/SM, one wave
    gq_kernel<<<blocks, THREADS>>>(z, eps, prior, (float*)d_out, out_size);
}